// round 1
// baseline (speedup 1.0000x reference)
#include <cuda_runtime.h>
#include <cuda_bf16.h>

// SymmetryConstraint: mean over symmetric-class pairs (i<j, class equal, class in {0,1,2})
// of (x_i + x_j - 1)^2 + (y_i - y_j)^2.
//
// Closed form per (batch, class) group of size m with u = x - 0.5:
//   sum_{i<j} (u_i+u_j)^2 = (m-2)*sum(u^2) + (sum u)^2
//   sum_{i<j} (y_i-y_j)^2 = m*sum(y^2) - (sum y)^2
//   pairs = m*(m-1)/2
// => O(B*N) reduction instead of O(B*N^2).

#define NPTS   512
#define NBATCH 256

__device__ double       g_part_loss[NBATCH];
__device__ double       g_part_cnt[NBATCH];
__device__ unsigned int g_done = 0;   // zero-initialized; reset by last block each call

__global__ __launch_bounds__(NPTS)
void symconstraint_kernel(const float* __restrict__ kp,   // [B, N, 2]
                          const int*   __restrict__ cls,  // [B, N]
                          float*       __restrict__ out)  // [1]
{
    const int b = blockIdx.x;
    const int t = threadIdx.x;

    __shared__ float s_su[3], s_su2[3], s_sy[3], s_sy2[3];
    __shared__ int   s_cnt[3];
    __shared__ unsigned int s_rank;

    if (t < 3) {
        s_su[t] = 0.f; s_su2[t] = 0.f; s_sy[t] = 0.f; s_sy2[t] = 0.f; s_cnt[t] = 0;
    }
    __syncthreads();

    // One point per thread
    const float2 p = reinterpret_cast<const float2*>(kp)[b * NPTS + t];
    const int    c = cls[b * NPTS + t];

    if (c >= 0 && c <= 2) {
        const float u = p.x - 0.5f;
        atomicAdd(&s_su [c], u);
        atomicAdd(&s_su2[c], u * u);
        atomicAdd(&s_sy [c], p.y);
        atomicAdd(&s_sy2[c], p.y * p.y);
        atomicAdd(&s_cnt[c], 1);
    }
    __syncthreads();

    if (t == 0) {
        double loss = 0.0, cnt = 0.0;
        #pragma unroll
        for (int k = 0; k < 3; k++) {
            const int mi = s_cnt[k];
            if (mi >= 2) {
                const double m   = (double)mi;
                const double su  = (double)s_su[k];
                const double su2 = (double)s_su2[k];
                const double sy  = (double)s_sy[k];
                const double sy2 = (double)s_sy2[k];
                loss += (m - 2.0) * su2 + su * su + m * sy2 - sy * sy;
                cnt  += m * (m - 1.0) * 0.5;
            }
        }
        g_part_loss[b] = loss;
        g_part_cnt[b]  = cnt;
        __threadfence();                       // make partials visible device-wide
        s_rank = atomicAdd(&g_done, 1u);       // arrival order
    }
    __syncthreads();

    // Last block to arrive reduces all partials (parallel, 512 threads)
    if (s_rank == NBATCH - 1) {
        __threadfence();   // acquire side: see every block's partials

        double L = 0.0, C = 0.0;
        if (t < NBATCH) {
            L = g_part_loss[t];
            C = g_part_cnt[t];
        }
        // warp reduce
        #pragma unroll
        for (int o = 16; o > 0; o >>= 1) {
            L += __shfl_down_sync(0xffffffffu, L, o);
            C += __shfl_down_sync(0xffffffffu, C, o);
        }
        __shared__ double sL[16], sC[16];
        const int w    = t >> 5;
        const int lane = t & 31;
        if (lane == 0) { sL[w] = L; sC[w] = C; }
        __syncthreads();
        if (w == 0) {
            L = (lane < 16) ? sL[lane] : 0.0;
            C = (lane < 16) ? sC[lane] : 0.0;
            #pragma unroll
            for (int o = 8; o > 0; o >>= 1) {
                L += __shfl_down_sync(0xffffffffu, L, o);
                C += __shfl_down_sync(0xffffffffu, C, o);
            }
            if (lane == 0) {
                out[0] = (float)(L / (C > 1.0 ? C : 1.0));
                g_done = 0;   // reset for next (graph-replayed) call
            }
        }
    }
}

extern "C" void kernel_launch(void* const* d_in, const int* in_sizes, int n_in,
                              void* d_out, int out_size)
{
    const float* kp  = (const float*)d_in[0];   // predicted_keypoints [256,512,2] f32
    const int*   cls = (const int*)d_in[1];     // keypoint_classes   [256,512]   i32
    float*       out = (float*)d_out;

    symconstraint_kernel<<<NBATCH, NPTS>>>(kp, cls, out);
}

// round 2
// speedup vs baseline: 1.6667x; 1.6667x over previous
#include <cuda_runtime.h>
#include <cuda_bf16.h>

// SymmetryConstraint — closed form per (batch, class) group (u = x - 0.5):
//   sum_{i<j}(u_i+u_j)^2 = (m-2)*sum(u^2) + (sum u)^2
//   sum_{i<j}(y_i-y_j)^2 = m*sum(y^2) - (sum y)^2
//   pairs = m*(m-1)/2
// O(B*N) instead of O(B*N^2).
//
// Layout: one warp per batch row. 128 blocks x 64 threads = 256 warps = 256 batches.
// Register accumulation (no shared atomics), fp32 throughout, warp shuffles,
// last-arriving warp reduces the 256 per-batch partials (fixed order => deterministic).

#define NPTS    512
#define NBATCH  256
#define TPB     64            // 2 warps per block
#define NBLOCKS (NBATCH / 2)  // 128

__device__ float2       g_part[NBATCH];   // (loss, pair_count) per batch
__device__ unsigned int g_done = 0;       // arrival ticket; reset by last warp

__global__ __launch_bounds__(TPB)
void symconstraint_kernel(const float* __restrict__ kp,   // [B, N, 2] f32
                          const int*   __restrict__ cls,  // [B, N]    i32
                          float*       __restrict__ out)  // [1]
{
    const int warp  = threadIdx.x >> 5;
    const int lane  = threadIdx.x & 31;
    const int batch = blockIdx.x * 2 + warp;

    const float4* __restrict__ kp4  = reinterpret_cast<const float4*>(kp);
    const int2*   __restrict__ cls2 = reinterpret_cast<const int2*>(cls);

    // Each float4 covers 2 points; row has 256 float4 / 256 int2.
    const int rowf = batch * (NPTS / 2);   // float4 index base
    // Load everything first: 8 float4 + 8 int2, fully coalesced, MLP=16.
    float4 q[8];
    int2   c2[8];
    #pragma unroll
    for (int i = 0; i < 8; i++) {
        q[i]  = kp4 [rowf + i * 32 + lane];
        c2[i] = cls2[rowf + i * 32 + lane];
    }

    // Per-class register accumulators.
    float su[3]  = {0.f, 0.f, 0.f};
    float su2[3] = {0.f, 0.f, 0.f};
    float sy[3]  = {0.f, 0.f, 0.f};
    float sy2[3] = {0.f, 0.f, 0.f};
    int   cnt[3] = {0, 0, 0};

    #pragma unroll
    for (int i = 0; i < 8; i++) {
        // point A
        {
            const int   c  = c2[i].x;
            const float u  = q[i].x - 0.5f;
            const float yy = q[i].y;
            const float uu = u * u;
            const float y2 = yy * yy;
            #pragma unroll
            for (int k = 0; k < 3; k++) {
                const bool hit = (c == k);
                su[k]  += hit ? u  : 0.f;
                su2[k] += hit ? uu : 0.f;
                sy[k]  += hit ? yy : 0.f;
                sy2[k] += hit ? y2 : 0.f;
                cnt[k] += hit ? 1 : 0;
            }
        }
        // point B
        {
            const int   c  = c2[i].y;
            const float u  = q[i].z - 0.5f;
            const float yy = q[i].w;
            const float uu = u * u;
            const float y2 = yy * yy;
            #pragma unroll
            for (int k = 0; k < 3; k++) {
                const bool hit = (c == k);
                su[k]  += hit ? u  : 0.f;
                su2[k] += hit ? uu : 0.f;
                sy[k]  += hit ? yy : 0.f;
                sy2[k] += hit ? y2 : 0.f;
                cnt[k] += hit ? 1 : 0;
            }
        }
    }

    // Warp butterfly reduction of the 15 accumulators.
    #pragma unroll
    for (int o = 16; o > 0; o >>= 1) {
        #pragma unroll
        for (int k = 0; k < 3; k++) {
            su[k]  += __shfl_xor_sync(0xffffffffu, su[k],  o);
            su2[k] += __shfl_xor_sync(0xffffffffu, su2[k], o);
            sy[k]  += __shfl_xor_sync(0xffffffffu, sy[k],  o);
            sy2[k] += __shfl_xor_sync(0xffffffffu, sy2[k], o);
            cnt[k] += __shfl_xor_sync(0xffffffffu, cnt[k], o);
        }
    }

    // Lane 0: fp32 closed form, publish partial, take a ticket.
    unsigned int ticket = 0;
    if (lane == 0) {
        float loss = 0.f, pc = 0.f;
        #pragma unroll
        for (int k = 0; k < 3; k++) {
            const float m = (float)cnt[k];
            if (cnt[k] >= 2) {
                loss += (m - 2.f) * su2[k] + su[k] * su[k]
                      +  m        * sy2[k] - sy[k] * sy[k];
                pc   += m * (m - 1.f) * 0.5f;
            }
        }
        g_part[batch] = make_float2(loss, pc);
        __threadfence();                       // publish before ticket
        ticket = atomicAdd(&g_done, 1u);
    }
    ticket = __shfl_sync(0xffffffffu, ticket, 0);

    // Last-arriving warp reduces all 256 partials in a fixed order.
    if (ticket == NBATCH - 1) {
        __threadfence();                       // acquire: see all partials

        const float4* __restrict__ gp4 = reinterpret_cast<const float4*>(g_part);
        float L = 0.f, C = 0.f;
        #pragma unroll
        for (int i = 0; i < 4; i++) {          // 128 float4 = 256 float2
            const float4 v = __ldcg(&gp4[i * 32 + lane]);
            L += v.x + v.z;
            C += v.y + v.w;
        }
        #pragma unroll
        for (int o = 16; o > 0; o >>= 1) {
            L += __shfl_xor_sync(0xffffffffu, L, o);
            C += __shfl_xor_sync(0xffffffffu, C, o);
        }
        if (lane == 0) {
            out[0] = L / fmaxf(C, 1.0f);
            g_done = 0;                        // reset for next graph replay
        }
    }
}

extern "C" void kernel_launch(void* const* d_in, const int* in_sizes, int n_in,
                              void* d_out, int out_size)
{
    const float* kp  = (const float*)d_in[0];
    const int*   cls = (const int*)d_in[1];
    float*       out = (float*)d_out;

    symconstraint_kernel<<<NBLOCKS, TPB>>>(kp, cls, out);
}

// round 6
// speedup vs baseline: 1.7481x; 1.0489x over previous
#include <cuda_runtime.h>
#include <cuda_bf16.h>

// SymmetryConstraint — closed form per (batch, class) group (u = x - 0.5):
//   sum_{i<j}(u_i+u_j)^2 = (m-2)*sum(u^2) + (sum u)^2
//   sum_{i<j}(y_i-y_j)^2 = m*sum(y^2) - (sum y)^2
//   pairs = m*(m-1)/2
//
// R3: 64 blocks x 256 threads. Each block owns 4 batches (2 warps per batch,
// 8 points per lane). One partial + ONE global atomic ticket per block
// (64 same-address atomics instead of 256 — that serialized tail dominated R2).

#define NPTS    512
#define NBATCH  256
#define TPB     256           // 8 warps
#define BPB     4             // batches per block
#define NBLOCKS (NBATCH / BPB)  // 64

__device__ float2       g_part[NBLOCKS];  // (loss, pair_count) per block
__device__ unsigned int g_done = 0;       // ticket; reset by last block

__global__ __launch_bounds__(TPB)
void symconstraint_kernel(const float* __restrict__ kp,   // [B, N, 2] f32
                          const int*   __restrict__ cls,  // [B, N]    i32
                          float*       __restrict__ out)  // [1]
{
    const int t    = threadIdx.x;
    const int warp = t >> 5;         // 0..7
    const int lane = t & 31;
    const int batch_local = warp >> 1;        // 0..3
    const int half        = warp & 1;         // which half of the batch row
    const int batch       = blockIdx.x * BPB + batch_local;

    const float4* __restrict__ kp4  = reinterpret_cast<const float4*>(kp);
    const int2*   __restrict__ cls2 = reinterpret_cast<const int2*>(cls);

    // Row = 256 float4 / 256 int2. This warp covers half*128 .. half*128+127.
    const int base = batch * (NPTS / 2) + half * 128;

    float4 q[4];
    int2   c2[4];
    #pragma unroll
    for (int i = 0; i < 4; i++) {
        q[i]  = kp4 [base + i * 32 + lane];
        c2[i] = cls2[base + i * 32 + lane];
    }

    float su[3]  = {0.f, 0.f, 0.f};
    float su2[3] = {0.f, 0.f, 0.f};
    float sy[3]  = {0.f, 0.f, 0.f};
    float sy2[3] = {0.f, 0.f, 0.f};
    int   cnt[3] = {0, 0, 0};

    #pragma unroll
    for (int i = 0; i < 4; i++) {
        {   // point A
            const int   c  = c2[i].x;
            const float u  = q[i].x - 0.5f;
            const float yy = q[i].y;
            const float uu = u * u, y2 = yy * yy;
            #pragma unroll
            for (int k = 0; k < 3; k++) {
                const bool h = (c == k);
                su[k] += h ? u : 0.f;   su2[k] += h ? uu : 0.f;
                sy[k] += h ? yy : 0.f;  sy2[k] += h ? y2 : 0.f;
                cnt[k] += h ? 1 : 0;
            }
        }
        {   // point B
            const int   c  = c2[i].y;
            const float u  = q[i].z - 0.5f;
            const float yy = q[i].w;
            const float uu = u * u, y2 = yy * yy;
            #pragma unroll
            for (int k = 0; k < 3; k++) {
                const bool h = (c == k);
                su[k] += h ? u : 0.f;   su2[k] += h ? uu : 0.f;
                sy[k] += h ? yy : 0.f;  sy2[k] += h ? y2 : 0.f;
                cnt[k] += h ? 1 : 0;
            }
        }
    }

    // Warp butterfly over the 15 accumulators.
    #pragma unroll
    for (int o = 16; o > 0; o >>= 1) {
        #pragma unroll
        for (int k = 0; k < 3; k++) {
            su[k]  += __shfl_xor_sync(0xffffffffu, su[k],  o);
            su2[k] += __shfl_xor_sync(0xffffffffu, su2[k], o);
            sy[k]  += __shfl_xor_sync(0xffffffffu, sy[k],  o);
            sy2[k] += __shfl_xor_sync(0xffffffffu, sy2[k], o);
            cnt[k] += __shfl_xor_sync(0xffffffffu, cnt[k], o);
        }
    }

    // Stash per-warp sums (cnt fits exactly in fp32).
    __shared__ float s_acc[8][16];   // [warp][15 used, padded]
    __shared__ float s_loss[BPB], s_cnt[BPB];
    __shared__ float2 s_block;
    __shared__ unsigned int s_ticket;

    if (lane == 0) {
        #pragma unroll
        for (int k = 0; k < 3; k++) {
            s_acc[warp][k]      = su[k];
            s_acc[warp][3 + k]  = su2[k];
            s_acc[warp][6 + k]  = sy[k];
            s_acc[warp][9 + k]  = sy2[k];
            s_acc[warp][12 + k] = (float)cnt[k];
        }
    }
    __syncthreads();

    // Threads 0..3: combine the two half-warps of batch t, closed form in fp32.
    if (t < BPB) {
        const float* a = s_acc[2 * t];
        const float* b = s_acc[2 * t + 1];
        float loss = 0.f, pc = 0.f;
        #pragma unroll
        for (int k = 0; k < 3; k++) {
            const float tsu  = a[k]      + b[k];
            const float tsu2 = a[3 + k]  + b[3 + k];
            const float tsy  = a[6 + k]  + b[6 + k];
            const float tsy2 = a[9 + k]  + b[9 + k];
            const float m    = a[12 + k] + b[12 + k];
            if (m >= 2.f) {
                loss += (m - 2.f) * tsu2 + tsu * tsu
                      +  m        * tsy2 - tsy * tsy;
                pc   += m * (m - 1.f) * 0.5f;
            }
        }
        s_loss[t] = loss;
        s_cnt[t]  = pc;
    }
    __syncthreads();

    // Thread 0: block total, publish, take ticket.
    if (t == 0) {
        float L = s_loss[0] + s_loss[1] + s_loss[2] + s_loss[3];
        float C = s_cnt[0]  + s_cnt[1]  + s_cnt[2]  + s_cnt[3];
        s_block = make_float2(L, C);
        g_part[blockIdx.x] = make_float2(L, C);
        __threadfence();                      // publish before ticket
        s_ticket = atomicAdd(&g_done, 1u);
    }
    __syncthreads();

    // Last block: warp 0 reduces all 64 partials in a fixed order.
    if (s_ticket == NBLOCKS - 1 && warp == 0) {
        __threadfence();                      // acquire: see all partials

        const float4* __restrict__ gp4 = reinterpret_cast<const float4*>(g_part);
        const float4 v = __ldcg(&gp4[lane]);  // 32 float4 = 64 float2
        float L = v.x + v.z;
        float C = v.y + v.w;
        #pragma unroll
        for (int o = 16; o > 0; o >>= 1) {
            L += __shfl_xor_sync(0xffffffffu, L, o);
            C += __shfl_xor_sync(0xffffffffu, C, o);
        }
        if (lane == 0) {
            out[0] = L / fmaxf(C, 1.0f);
            g_done = 0;                       // reset for next graph replay
        }
    }
}

extern "C" void kernel_launch(void* const* d_in, const int* in_sizes, int n_in,
                              void* d_out, int out_size)
{
    const float* kp  = (const float*)d_in[0];
    const int*   cls = (const int*)d_in[1];
    float*       out = (float*)d_out;

    symconstraint_kernel<<<NBLOCKS, TPB>>>(kp, cls, out);
}